// round 11
// baseline (speedup 1.0000x reference)
#include <cuda_runtime.h>
#include <math_constants.h>

#define NB 96
#define ND 128
#define NPAIR (NB * NB)
#define NCLS 8
#define NUND 4560                 // NB*(NB-1)/2 undirected pairs
#define BTHR 1024
#define MAXBLK 64
#define POSC 4608                 // >= worst-case undirected pos (4560) + padding

// dynamic smem (bytes): sE 49152 | sPD 18432 | sPM 18432 = 86016
#define DYN_SMEM (NB * ND * 4 + POSC * 4 + POSC * 4)

// ---------------- device scratch (no allocations allowed) ----------------
__device__ float g_Dm[NPAIR];                   // diag never read (masked everywhere)
__device__ float g_bP[MAXBLK], g_bN[MAXBLK];    // per-block pos/neg distance partials
__device__ int   g_ctrA = 0, g_ctrB = 0;
__device__ volatile int g_flagA = 0;
__device__ float g_pQ[MAXBLK], g_pT[MAXBLK];
__device__ unsigned g_pQC[MAXBLK], g_pTC[MAXBLK];

__global__ void __launch_bounds__(BTHR, 1)
kFused(const float* __restrict__ E, const void* __restrict__ labp,
       float* __restrict__ out) {
    extern __shared__ __align__(16) unsigned char dynRaw[];
    float* sE  = reinterpret_cast<float*>(dynRaw);                          // [NB*ND]
    float* sPD = reinterpret_cast<float*>(dynRaw + NB * ND * 4);            // [POSC]
    int*   sPM = reinterpret_cast<int*>(dynRaw + NB * ND * 4 + POSC * 4);   // [POSC]

    __shared__ int   sLab[NB];
    __shared__ int   sHist[NCLS];
    __shared__ int   sIs64;
    __shared__ unsigned sWT[32 * 4], sWB[32 * 4], sTot4[4];
    __shared__ int   sOff[NCLS + 1];
    __shared__ float sF1[32], sF2[32];
    __shared__ unsigned sC1[32], sC2[32];
    __shared__ float sThr;
    __shared__ int   sLast;

    const int t = threadIdx.x;
    const int wid = t >> 5, lid = t & 31;
    const int nblk = gridDim.x;

    // ---- issue ALL E loads first (independent of labels; DRAM latency overlaps) ----
    const float4 e0 = ((const float4*)E)[t];
    const float4 e1 = ((const float4*)E)[t + BTHR];
    const float4 e2 = ((const float4*)E)[t + 2 * BTHR];

    // ---- labels: int64 (values<8 => high words 0) or int32 (JAX demotion) ----
    if (t < NCLS) sHist[t] = 0;
    if (t == 0) sIs64 = 1;
    __syncthreads();
    if (t < NB / 2 && ((const int*)labp)[2 * t + 1] != 0) sIs64 = 0;   // benign race
    __syncthreads();
    if (t < NB) {
        int l = sIs64 ? (int)((const long long*)labp)[t] : ((const int*)labp)[t];
        sLab[t] = l;
        atomicAdd(&sHist[l & 7], 1);
    }
    // stage E into smem (stalls only until the early loads land)
    ((float4*)sE)[t] = e0;
    ((float4*)sE)[t + BTHR] = e1;
    ((float4*)sE)[t + 2 * BTHR] = e2;
    __syncthreads();            // sLab, sHist, sE all visible

    // ======== counting-sort structure (labels only) ========
    unsigned pk[4] = {0u, 0u, 0u, 0u};    // 8 class counts as 16-bit fields
    {
        int ii = t / NB, jj = t - (t / NB) * NB;
#pragma unroll 1
        for (int it = 0; it < NPAIR / BTHR; it++) {
            if (ii < jj) {
                int li = sLab[ii];
                if (li == sLab[jj]) {
                    unsigned add = 1u << ((li & 1) * 16);
                    int r = li >> 1;
                    pk[0] += (r == 0) ? add : 0u;
                    pk[1] += (r == 1) ? add : 0u;
                    pk[2] += (r == 2) ? add : 0u;
                    pk[3] += (r == 3) ? add : 0u;
                }
            }
            jj += 64; ii += 10; if (jj >= NB) { jj -= NB; ii++; }
        }
    }
    unsigned ex[4];                        // intra-warp exclusive, packed
#pragma unroll
    for (int r = 0; r < 4; r++) {
        unsigned inc = pk[r];
#pragma unroll
        for (int o = 1; o < 32; o <<= 1) {
            unsigned x = __shfl_up_sync(0xffffffffu, inc, o);
            if (lid >= o) inc += x;
        }
        ex[r] = inc - pk[r];
        if (lid == 31) sWT[wid * 4 + r] = inc;
    }
    __syncthreads();
    if (wid == 0) {                        // cross-warp scan (32 warps -> 32 lanes)
#pragma unroll
        for (int r = 0; r < 4; r++) {
            unsigned own = sWT[lid * 4 + r];
            unsigned inc = own;
#pragma unroll
            for (int o = 1; o < 32; o <<= 1) {
                unsigned x = __shfl_up_sync(0xffffffffu, inc, o);
                if (lid >= o) inc += x;
            }
            sWB[lid * 4 + r] = inc - own;
            if (lid == 31) sTot4[r] = inc;
        }
    }
    __syncthreads();

    int start[NCLS];                       // my scatter cursors
    int base8;
    {
        int b = 0;
#pragma unroll
        for (int c = 0; c < NCLS; c++) {
            int tot = (int)((sTot4[c >> 1] >> ((c & 1) * 16)) & 0xFFFFu);
            int wb  = (int)((sWB[wid * 4 + (c >> 1)] >> ((c & 1) * 16)) & 0xFFFFu);
            int eo  = (int)((ex[c >> 1] >> ((c & 1) * 16)) & 0xFFFFu);
            start[c] = b + wb + eo;
            if (t == 0) sOff[c] = b;
            b = (b + tot + 3) & ~3;        // 4-elem aligned segments
        }
        if (t == 0) sOff[NCLS] = b;
        base8 = b;
    }
    for (int x = t; x < base8; x += BTHR) { sPD[x] = -CUDART_INF_F; sPM[x] = 0; }

    // ================= Phase 1: distances from smem E (warp per pair) =============
    float myPos = 0.f, myNeg = 0.f;
    for (int p = blockIdx.x * 32 + wid; p < NUND; p += nblk * 32) {
        // decode undirected pair p -> (i, j), i < j ; offset(i) = i*(191-i)/2
        float s = sqrtf((float)(36481 - 8 * p));
        int i = (int)((191.0f - s) * 0.5f);
        while ((i + 1) * (191 - (i + 1)) / 2 <= p) ++i;
        while (i * (191 - i) / 2 > p) --i;
        int j = i + 1 + (p - i * (191 - i) / 2);
        const float4 a = ((const float4*)(sE + i * ND))[lid];
        const float4 b = ((const float4*)(sE + j * ND))[lid];
        float dx = a.x - b.x, dy = a.y - b.y, dz = a.z - b.z, dw = a.w - b.w;
        float d2 = dx * dx + dy * dy + dz * dz + dw * dw;
#pragma unroll
        for (int o = 16; o; o >>= 1) d2 += __shfl_down_sync(0xffffffffu, d2, o);
        if (lid == 0) {
            float dm = sqrtf(fmaxf(d2, 0.f) + 1e-16f);
            g_Dm[i * NB + j] = dm;
            g_Dm[j * NB + i] = dm;
            if (sLab[i] == sLab[j]) myPos += dm; else myNeg += dm;
        }
    }
    if (lid == 0) { sF1[wid] = myPos; sF2[wid] = myNeg; }
    __syncthreads();

    // ================= barrier A (64 arrivals; plain volatile poll) ===============
    if (t == 0) {
        float pS = 0.f, nS = 0.f;
#pragma unroll
        for (int w = 0; w < 32; w++) { pS += sF1[w]; nS += sF2[w]; }
        g_bP[blockIdx.x] = pS; g_bN[blockIdx.x] = nS;
        __threadfence();
        if (atomicAdd(&g_ctrA, 1) == nblk - 1) g_flagA = 1;
        else while (g_flagA == 0) { }      // volatile L2 poll (~300cyc/iter)
        __threadfence();
    }
    __syncthreads();

    // ---- thr (warp 0; deterministic fixed order => identical in every block) ----
    if (wid == 0) {
        float pS = 0.f, nS = 0.f;
        for (int w = lid; w < nblk; w += 32) { pS += g_bP[w]; nS += g_bN[w]; }
#pragma unroll
        for (int o = 16; o; o >>= 1) {
            pS += __shfl_down_sync(0xffffffffu, pS, o);
            nS += __shfl_down_sync(0xffffffffu, nS, o);
        }
        if (lid == 0) {
            int s2 = 0;
#pragma unroll
            for (int c = 0; c < NCLS; c++) { int h = sHist[c]; s2 += h * h; }
            float cpos = (float)(s2 - NB);          // directed same-label pairs
            float cneg = (float)(NPAIR - s2);       // directed diff-label pairs
            float mu = (cpos > 0.f && cneg > 0.f)
                       ? ((2.f * nS) / cneg - (2.f * pS) / cpos) : 0.f;
            sThr = fmaxf(mu, 0.f);
        }
    }

    // ---- scatter pos pairs (same traversal order as counting pass) ----
    {
        int ii = t / NB, jj = t - (t / NB) * NB, idx = t;
#pragma unroll 1
        for (int it = 0; it < NPAIR / BTHR; it++) {
            if (ii < jj) {
                int li = sLab[ii];
                if (li == sLab[jj]) {
                    int s2 = 0;
#pragma unroll
                    for (int c = 0; c < NCLS; c++) { if (li == c) s2 = start[c]++; }
                    sPD[s2] = g_Dm[idx];
                    sPM[s2] = ii | (jj << 8) | (li << 16);
                }
            }
            jj += 64; ii += 10; idx += BTHR; if (jj >= NB) { jj -= NB; ii++; }
        }
    }
    __syncthreads();

    const float thr = sThr, thrh = 0.5f * thr;

    // ================= Phase 2: quad (undirected neg, weighted) + triplet =========
    float qs = 0.f, ts = 0.f; unsigned qc = 0, tc = 0;
    const int gt = blockIdx.x * BTHR + t;
    const int GT = nblk * BTHR;

    // quad item = (pair idx, segment seg, half); active iff undirected neg pair
    const int qTot = NPAIR * NCLS * 2;
    for (int e = gt; e < qTot; e += GT) {
        int idx = e >> 4;
        int ii = idx / NB, jj = idx - ii * NB;
        if (ii >= jj) continue;
        int li = sLab[ii], lj = sLab[jj];
        if (li == lj) continue;                    // not a negative pair
        float b = g_Dm[idx];                       // L2
        int seg = (e >> 1) & 7, half = e & 1;
        int lo = sOff[seg], hi = sOff[seg + 1];
        int hlen = ((hi - lo + 7) >> 3) << 2;      // 4-aligned half length
        int xs = lo + half * hlen;
        int xe = min(xs + hlen, hi);
        int wi = 2 - (seg == li) - (seg == lj);    // in {1,2}
        float ls = 0.f; int lc = 0;
        for (int x = xs; x < xe; x += 4) {
            const float4 v = *reinterpret_cast<const float4*>(&sPD[x]);
            float d0 = b - v.x, d1 = b - v.y, d2 = b - v.z, d3 = b - v.w;
            if (d0 < thrh) { lc++; ls += fmaxf(d0, 0.f); }
            if (d1 < thrh) { lc++; ls += fmaxf(d1, 0.f); }
            if (d2 < thrh) { lc++; ls += fmaxf(d2, 0.f); }
            if (d3 < thrh) { lc++; ls += fmaxf(d3, 0.f); }
        }
        qs = fmaf((float)wi, ls, qs);
        qc += (unsigned)(wi * lc);
    }

    // triplet: item = (padded pos slot pp, negative k); both anchor orientations
    for (int e = gt; e < base8 * NB; e += GT) {
        int pp = e / NB, k = e - pp * NB;
        int meta = sPM[pp];
        int ai = meta & 255, aj = (meta >> 8) & 255, c = meta >> 16;
        float dij = sPD[pp];                       // -INF pads => +INF diffs => skipped
        if (sLab[k] != c) {
            float tv1 = g_Dm[ai * NB + k] - dij;
            float tv2 = g_Dm[aj * NB + k] - dij;
            if (tv1 < thr) { tc++; ts += fmaxf(tv1, 0.f); }
            if (tv2 < thr) { tc++; ts += fmaxf(tv2, 0.f); }
        }
    }

    // ================= Phase 3: reduce + combine =================
#pragma unroll
    for (int o = 16; o; o >>= 1) {
        qs += __shfl_down_sync(0xffffffffu, qs, o);
        ts += __shfl_down_sync(0xffffffffu, ts, o);
        qc += __shfl_down_sync(0xffffffffu, qc, o);
        tc += __shfl_down_sync(0xffffffffu, tc, o);
    }
    if ((t & 31) == 0) { sF1[wid] = qs; sF2[wid] = ts; sC1[wid] = qc; sC2[wid] = tc; }
    __syncthreads();
    if (t < 32) {
        qs = sF1[t]; ts = sF2[t]; qc = sC1[t]; tc = sC2[t];
#pragma unroll
        for (int o = 16; o; o >>= 1) {
            qs += __shfl_down_sync(0xffffffffu, qs, o);
            ts += __shfl_down_sync(0xffffffffu, ts, o);
            qc += __shfl_down_sync(0xffffffffu, qc, o);
            tc += __shfl_down_sync(0xffffffffu, tc, o);
        }
    }
    __syncthreads();
    if (t == 0) {
        g_pQ[blockIdx.x] = qs; g_pT[blockIdx.x] = ts;
        g_pQC[blockIdx.x] = qc; g_pTC[blockIdx.x] = tc;
        __threadfence();
        sLast = (atomicAdd(&g_ctrB, 1) == nblk - 1);
    }
    __syncthreads();
    if (!sLast) return;

    if (t < 32) {
        float a = 0.f, b = 0.f; unsigned c1 = 0, c2 = 0;
        for (int w = t; w < nblk; w += 32) {
            a += g_pQ[w]; b += g_pT[w]; c1 += g_pQC[w]; c2 += g_pTC[w];
        }
#pragma unroll
        for (int o = 16; o; o >>= 1) {
            a  += __shfl_down_sync(0xffffffffu, a, o);
            b  += __shfl_down_sync(0xffffffffu, b, o);
            c1 += __shfl_down_sync(0xffffffffu, c1, o);
            c2 += __shfl_down_sync(0xffffffffu, c2, o);
        }
        if (t == 0) {
            float tl = (c2 > 0) ? b / (float)c2 : 0.f;
            float ql = (c1 > 0) ? a / (float)c1 : 0.f;
            out[0] = tl + ql;
            g_ctrA = 0; g_ctrB = 0; g_flagA = 0;    // reset for next replay
        }
    }
}

extern "C" void kernel_launch(void* const* d_in, const int* in_sizes, int n_in,
                              void* d_out, int out_size) {
    const float* E = (const float*)d_in[0];
    const void* lab = d_in[1];
    (void)in_sizes; (void)n_in; (void)out_size;
    cudaFuncSetAttribute(kFused, cudaFuncAttributeMaxDynamicSharedMemorySize, DYN_SMEM);
    int sms = 148;
    cudaDeviceGetAttribute(&sms, cudaDevAttrMultiProcessorCount, 0);
    // clamp grid to PROVABLE single-wave residency (spin barrier safety)
    int perSM = 1;
    cudaOccupancyMaxActiveBlocksPerMultiprocessor(&perSM, kFused, BTHR, DYN_SMEM);
    if (perSM < 1) perSM = 1;
    long cap = (long)perSM * sms;
    int grid = sms < MAXBLK ? sms : MAXBLK;
    if (grid > cap) grid = (int)cap;
    if (grid < 1) grid = 1;
    kFused<<<grid, BTHR, DYN_SMEM>>>(E, lab, (float*)d_out);
}

// round 12
// speedup vs baseline: 1.2487x; 1.2487x over previous
#include <cuda_runtime.h>
#include <math_constants.h>

#define NB 96
#define ND 128
#define NPAIR (NB * NB)
#define NCLS 8
#define NUND 4560                 // NB*(NB-1)/2 undirected pairs
#define BTHR 1024
#define MAXBLK 160
#define POSC 4608                 // >= worst-case undirected pos (4560) + padding
#define FULLM 0xffffffffu

// ---------------- device scratch (no allocations allowed) ----------------
__device__ float g_Dm[NPAIR];                   // diag never read (masked everywhere)
__device__ float g_bP[MAXBLK], g_bN[MAXBLK];    // per-block pos/neg distance partials
__device__ float g_pQ[MAXBLK], g_pT[MAXBLK];
__device__ unsigned g_pQC[MAXBLK], g_pTC[MAXBLK];
__device__ volatile int g_flag[MAXBLK];         // 0 -> 1 (barrier A) -> 2 (done); block 0 resets

__global__ void __launch_bounds__(BTHR, 1)
kFused(const float* __restrict__ E, const void* __restrict__ labp,
       float* __restrict__ out) {
    __shared__ __align__(16) float sPD[POSC];   // 18 KB
    __shared__ int   sPM[POSC];                 // 18 KB
    __shared__ int   sLab[NB];
    __shared__ int   sIs64;
    __shared__ int   sRowCnt[NB];               // counts, then per-class row prefix
    __shared__ int   sRowStart[NB];
    __shared__ int   sOff[NCLS + 1];
    __shared__ float sF1[32], sF2[32];
    __shared__ unsigned sC1[32], sC2[32];
    __shared__ float sThr;

    const int t = threadIdx.x;
    const int wid = t >> 5, lid = t & 31;
    const int bid = blockIdx.x;
    const int nblk = gridDim.x;

    // ---- labels: int64 (values<8 => high words 0) or int32 (JAX demotion) ----
    if (t == 0) sIs64 = 1;
    __syncthreads();
    if (t < NB / 2 && ((const int*)labp)[2 * t + 1] != 0) sIs64 = 0;   // benign race
    __syncthreads();
    if (t < NB) sLab[t] = sIs64 ? (int)((const long long*)labp)[t]
                                : ((const int*)labp)[t];
    __syncthreads();

    // ---- pad init (whole capacity; real slots overwritten by scatter) ----
    for (int x = t; x < POSC; x += BTHR) { sPD[x] = -CUDART_INF_F; sPM[x] = 0; }

    // ---- row-ballot pos counting: warp w owns rows w, w+32, w+64 ----
#pragma unroll
    for (int rr = 0; rr < 3; rr++) {
        int r = wid + 32 * rr;
        int lr = sLab[r];
        int cnt = 0;
#pragma unroll
        for (int ch = 0; ch < 3; ch++) {
            int jj = ch * 32 + lid;
            unsigned m = __ballot_sync(FULLM, (jj > r) && (sLab[jj] == lr));
            cnt += __popc(m);
        }
        if (lid == 0) sRowCnt[r] = cnt;
    }

    // ================= Phase 1: distance matrix (warp per pair) =================
    float myPos = 0.f, myNeg = 0.f;
    for (int p = bid * 32 + wid; p < NUND; p += nblk * 32) {
        // decode undirected pair p -> (i, j), i < j ; offset(i) = i*(191-i)/2
        float s = sqrtf((float)(36481 - 8 * p));
        int i = (int)((191.0f - s) * 0.5f);
        while ((i + 1) * (191 - (i + 1)) / 2 <= p) ++i;
        while (i * (191 - i) / 2 > p) --i;
        int j = i + 1 + (p - i * (191 - i) / 2);
        const float4 a = ((const float4*)(E + i * ND))[lid];
        const float4 b = ((const float4*)(E + j * ND))[lid];
        float dx = a.x - b.x, dy = a.y - b.y, dz = a.z - b.z, dw = a.w - b.w;
        float d2 = dx * dx + dy * dy + dz * dz + dw * dw;
#pragma unroll
        for (int o = 16; o; o >>= 1) d2 += __shfl_down_sync(FULLM, d2, o);
        if (lid == 0) {
            float dm = sqrtf(fmaxf(d2, 0.f) + 1e-16f);
            g_Dm[i * NB + j] = dm;
            g_Dm[j * NB + i] = dm;
            if (sLab[i] == sLab[j]) myPos += dm; else myNeg += dm;
        }
    }
    if (lid == 0) { sF1[wid] = myPos; sF2[wid] = myNeg; }
    __syncthreads();                               // publishes Dm STGs, sRowCnt

    // ================= barrier A arrive + warp-0 overlapped build ================
    if (wid == 0) {
        if (lid == 0) {
            float pS = 0.f, nS = 0.f;
#pragma unroll
            for (int w = 0; w < 32; w++) { pS += sF1[w]; nS += sF2[w]; }
            g_bP[bid] = pS; g_bN[bid] = nS;
            __threadfence();
            g_flag[bid] = 1;                       // parallel arrival (no atomics)
        }
        __syncwarp();

        // packed per-class exclusive scan over 96 row counts (label-only work,
        // executed while other blocks are still arriving)
        unsigned c0 = 0, c1 = 0, c2 = 0, c3 = 0;
#pragma unroll
        for (int ch = 0; ch < 3; ch++) {
            int r = ch * 32 + lid;
            int cnt = sRowCnt[r];
            int cr = sLab[r];
            unsigned f = (unsigned)cnt << ((cr & 1) * 16);
            unsigned p0 = ((cr >> 1) == 0) ? f : 0u;
            unsigned p1 = ((cr >> 1) == 1) ? f : 0u;
            unsigned p2 = ((cr >> 1) == 2) ? f : 0u;
            unsigned p3 = ((cr >> 1) == 3) ? f : 0u;
            unsigned i0 = p0, i1 = p1, i2 = p2, i3 = p3;
#pragma unroll
            for (int o = 1; o < 32; o <<= 1) {
                unsigned x0 = __shfl_up_sync(FULLM, i0, o);
                unsigned x1 = __shfl_up_sync(FULLM, i1, o);
                unsigned x2 = __shfl_up_sync(FULLM, i2, o);
                unsigned x3 = __shfl_up_sync(FULLM, i3, o);
                if (lid >= o) { i0 += x0; i1 += x1; i2 += x2; i3 += x3; }
            }
            unsigned e0 = i0 - p0 + c0, e1 = i1 - p1 + c1;
            unsigned e2 = i2 - p2 + c2, e3 = i3 - p3 + c3;
            unsigned sel = ((cr >> 1) == 0) ? e0 : ((cr >> 1) == 1) ? e1
                         : ((cr >> 1) == 2) ? e2 : e3;
            sRowCnt[r] = (int)((sel >> ((cr & 1) * 16)) & 0xFFFFu);  // row prefix in class
            c0 += __shfl_sync(FULLM, i0, 31);
            c1 += __shfl_sync(FULLM, i1, 31);
            c2 += __shfl_sync(FULLM, i2, 31);
            c3 += __shfl_sync(FULLM, i3, 31);
        }
        const int tt0 = (int)(c0 & 0xFFFFu), tt1 = (int)(c0 >> 16);
        const int tt2 = (int)(c1 & 0xFFFFu), tt3 = (int)(c1 >> 16);
        const int tt4 = (int)(c2 & 0xFFFFu), tt5 = (int)(c2 >> 16);
        const int tt6 = (int)(c3 & 0xFFFFu), tt7 = (int)(c3 >> 16);
        int bs0, bs1, bs2, bs3, bs4, bs5, bs6, bs7, b = 0;
        bs0 = b; b = (b + tt0 + 3) & ~3;  bs1 = b; b = (b + tt1 + 3) & ~3;
        bs2 = b; b = (b + tt2 + 3) & ~3;  bs3 = b; b = (b + tt3 + 3) & ~3;
        bs4 = b; b = (b + tt4 + 3) & ~3;  bs5 = b; b = (b + tt5 + 3) & ~3;
        bs6 = b; b = (b + tt6 + 3) & ~3;  bs7 = b; b = (b + tt7 + 3) & ~3;
        if (lid == 0) {
            sOff[0] = bs0; sOff[1] = bs1; sOff[2] = bs2; sOff[3] = bs3;
            sOff[4] = bs4; sOff[5] = bs5; sOff[6] = bs6; sOff[7] = bs7;
            sOff[8] = b;
        }
#pragma unroll
        for (int ch = 0; ch < 3; ch++) {
            int r = ch * 32 + lid;
            int cr = sLab[r];
            int bc = bs0;
            bc = (cr == 1) ? bs1 : bc;  bc = (cr == 2) ? bs2 : bc;
            bc = (cr == 3) ? bs3 : bc;  bc = (cr == 4) ? bs4 : bc;
            bc = (cr == 5) ? bs5 : bc;  bc = (cr == 6) ? bs6 : bc;
            bc = (cr == 7) ? bs7 : bc;
            sRowStart[r] = bc + sRowCnt[r];
        }

        // ---- poll barrier A (all flags >= 1) ----
        for (;;) {
            int ok = 1;
            for (int x = lid; x < nblk; x += 32) ok &= (g_flag[x] >= 1);
            if (__ballot_sync(FULLM, ok) == FULLM) break;
        }
        __threadfence();

        // ---- thr (deterministic fixed order => identical in every block) ----
        float pS = 0.f, nS = 0.f;
        for (int x = lid; x < nblk; x += 32) { pS += g_bP[x]; nS += g_bN[x]; }
#pragma unroll
        for (int o = 16; o; o >>= 1) {
            pS += __shfl_down_sync(FULLM, pS, o);
            nS += __shfl_down_sync(FULLM, nS, o);
        }
        if (lid == 0) {
            int nposU = tt0 + tt1 + tt2 + tt3 + tt4 + tt5 + tt6 + tt7;
            float cpos = 2.f * (float)nposU;                 // directed same-label pairs
            float cneg = (float)(NPAIR - NB) - cpos;         // directed diff-label pairs
            float mu = (cpos > 0.f && cneg > 0.f)
                       ? ((2.f * nS) / cneg - (2.f * pS) / cpos) : 0.f;
            sThr = fmaxf(mu, 0.f);
        }
    }
    __syncthreads();
    const int base8 = sOff[NCLS];

    // ---- ballot scatter: warp w owns rows w, w+32, w+64 ----
#pragma unroll
    for (int rr = 0; rr < 3; rr++) {
        int r = wid + 32 * rr;
        int lr = sLab[r];
        int run = sRowStart[r];
#pragma unroll
        for (int ch = 0; ch < 3; ch++) {
            int jj = ch * 32 + lid;
            bool pred = (jj > r) && (sLab[jj] == lr);
            unsigned m = __ballot_sync(FULLM, pred);
            if (pred) {
                int slot = run + __popc(m & ((1u << lid) - 1u));
                sPD[slot] = g_Dm[r * NB + jj];
                sPM[slot] = r | (jj << 8) | (lr << 16);
            }
            run += __popc(m);
        }
    }
    __syncthreads();

    const float thr = sThr, thrh = 0.5f * thr;

    // ================= Phase 2: quad (undirected neg, weighted) + triplet =========
    float qs = 0.f, ts = 0.f; unsigned qc = 0, tc = 0;
    const int gt = bid * BTHR + t;
    const int GT = nblk * BTHR;

    // quad item = (pair idx, segment seg, quarter); active iff undirected neg pair
    const int qTot = NPAIR * NCLS * 4;
    for (int e = gt; e < qTot; e += GT) {
        int idx = e >> 5;
        int ii = idx / NB, jj = idx - ii * NB;
        if (ii >= jj) continue;
        int li = sLab[ii], lj = sLab[jj];
        if (li == lj) continue;                    // not a negative pair
        float b = g_Dm[idx];                       // L2
        int seg = (e >> 2) & 7, quar = e & 3;
        int lo = sOff[seg], hi = sOff[seg + 1];
        int qlen = ((hi - lo + 15) >> 4) << 2;     // 4-aligned quarter length
        int xs = lo + quar * qlen;
        int xe = min(xs + qlen, hi);
        int wi = 2 - (seg == li) - (seg == lj);    // in {1,2}
        float ls = 0.f; int lc = 0;
        for (int x = xs; x < xe; x += 4) {
            const float4 v = *reinterpret_cast<const float4*>(&sPD[x]);
            float d0 = b - v.x, d1 = b - v.y, d2 = b - v.z, d3 = b - v.w;
            if (d0 < thrh) { lc++; ls += fmaxf(d0, 0.f); }
            if (d1 < thrh) { lc++; ls += fmaxf(d1, 0.f); }
            if (d2 < thrh) { lc++; ls += fmaxf(d2, 0.f); }
            if (d3 < thrh) { lc++; ls += fmaxf(d3, 0.f); }
        }
        qs = fmaf((float)wi, ls, qs);
        qc += (unsigned)(wi * lc);
    }

    // triplet: item = (padded pos slot pp, negative k); both anchor orientations
    for (int e = gt; e < base8 * NB; e += GT) {
        int pp = e / NB, k = e - pp * NB;
        int meta = sPM[pp];
        int ai = meta & 255, aj = (meta >> 8) & 255, c = meta >> 16;
        float dij = sPD[pp];                       // -INF pads => +INF diffs => skipped
        if (sLab[k] != c) {
            float tv1 = g_Dm[ai * NB + k] - dij;
            float tv2 = g_Dm[aj * NB + k] - dij;
            if (tv1 < thr) { tc++; ts += fmaxf(tv1, 0.f); }
            if (tv2 < thr) { tc++; ts += fmaxf(tv2, 0.f); }
        }
    }

    // ================= Phase 3: block reduce, publish, combine =================
#pragma unroll
    for (int o = 16; o; o >>= 1) {
        qs += __shfl_down_sync(FULLM, qs, o);
        ts += __shfl_down_sync(FULLM, ts, o);
        qc += __shfl_down_sync(FULLM, qc, o);
        tc += __shfl_down_sync(FULLM, tc, o);
    }
    if ((t & 31) == 0) { sF1[wid] = qs; sF2[wid] = ts; sC1[wid] = qc; sC2[wid] = tc; }
    __syncthreads();
    if (t == 0) {
        float a = 0.f, b2 = 0.f; unsigned u1 = 0, u2 = 0;
#pragma unroll
        for (int w = 0; w < 32; w++) { a += sF1[w]; b2 += sF2[w]; u1 += sC1[w]; u2 += sC2[w]; }
        g_pQ[bid] = a; g_pT[bid] = b2; g_pQC[bid] = u1; g_pTC[bid] = u2;
        __threadfence();
        g_flag[bid] = 2;                           // done (monotone)
    }
    if (bid != 0) return;                          // non-zero blocks exit

    // ---- block 0, warp 0: wait for all, combine, write, reset flags ----
    if (wid == 0) {
        for (;;) {
            int ok = 1;
            for (int x = lid; x < nblk; x += 32) ok &= (g_flag[x] == 2);
            if (__ballot_sync(FULLM, ok) == FULLM) break;
        }
        __threadfence();
        float a = 0.f, b2 = 0.f; unsigned u1 = 0, u2 = 0;
        for (int x = lid; x < nblk; x += 32) {
            a += g_pQ[x]; b2 += g_pT[x]; u1 += g_pQC[x]; u2 += g_pTC[x];
        }
#pragma unroll
        for (int o = 16; o; o >>= 1) {
            a  += __shfl_down_sync(FULLM, a, o);
            b2 += __shfl_down_sync(FULLM, b2, o);
            u1 += __shfl_down_sync(FULLM, u1, o);
            u2 += __shfl_down_sync(FULLM, u2, o);
        }
        if (lid == 0) {
            float tl = (u2 > 0) ? b2 / (float)u2 : 0.f;
            float ql = (u1 > 0) ? a / (float)u1 : 0.f;
            out[0] = tl + ql;
        }
        for (int x = lid; x < MAXBLK; x += 32) g_flag[x] = 0;   // reset for replay
    }
}

extern "C" void kernel_launch(void* const* d_in, const int* in_sizes, int n_in,
                              void* d_out, int out_size) {
    const float* E = (const float*)d_in[0];
    const void* lab = d_in[1];
    (void)in_sizes; (void)n_in; (void)out_size;
    int sms = 148;
    cudaDeviceGetAttribute(&sms, cudaDevAttrMultiProcessorCount, 0);
    // clamp grid to PROVABLE single-wave residency (poll barrier safety)
    int perSM = 1;
    cudaOccupancyMaxActiveBlocksPerMultiprocessor(&perSM, kFused, BTHR, 0);
    if (perSM < 1) perSM = 1;
    long cap = (long)perSM * sms;
    int grid = sms < MAXBLK ? sms : MAXBLK;
    if (grid > cap) grid = (int)cap;
    if (grid < 1) grid = 1;
    kFused<<<grid, BTHR>>>(E, lab, (float*)d_out);
}